// round 1
// baseline (speedup 1.0000x reference)
#include <cuda_runtime.h>
#include <cstdint>
#include <math.h>

// Problem constants (MiMoV2Moe: T tokens, H hidden, E experts, I intermediate, top-K)
#define T_TOK 4096
#define H_DIM 2048
#define E_NUM 32
#define I_DIM 1024
#define TOPK  8
#define P_NUM (T_TOK * TOPK)   // 32768 token-expert pairs

// ---------------- scratch (device globals: no allocation allowed) ----------------
__device__ int   g_topk_ids[P_NUM];
__device__ float g_topk_w[P_NUM];
__device__ int   g_cnt[E_NUM];
__device__ int   g_pos[E_NUM];
__device__ int   g_off[E_NUM + 1];
__device__ int   g_slot_token[P_NUM];
__device__ float g_slot_w[P_NUM];
__device__ int   g_pair2slot[P_NUM];
__device__ float g_hbuf[(size_t)P_NUM * I_DIM];  // 134 MB: silu(x@wg)*(x@wu) per pair
__device__ float g_dbuf[(size_t)P_NUM * H_DIM];  // 268 MB: weighted down-proj per pair

// ---------------- helpers ----------------
__device__ __forceinline__ uint32_t f2tf(float f) {
    uint32_t u;
    asm("cvt.rna.tf32.f32 %0, %1;" : "=r"(u) : "f"(f));
    return u;
}

__device__ __forceinline__ void mma8(float c[4], const uint32_t a[4], const uint32_t b[2]) {
    asm volatile(
        "mma.sync.aligned.m16n8k8.row.col.f32.tf32.tf32.f32 "
        "{%0,%1,%2,%3}, {%4,%5,%6,%7}, {%8,%9}, {%0,%1,%2,%3};\n"
        : "+f"(c[0]), "+f"(c[1]), "+f"(c[2]), "+f"(c[3])
        : "r"(a[0]), "r"(a[1]), "r"(a[2]), "r"(a[3]), "r"(b[0]), "r"(b[1]));
}

__device__ __forceinline__ float silu(float x) {
    return x * (1.0f / (1.0f + expf(-x)));
}

// ---------------- kernel 0: zero expert counters ----------------
__global__ void k_zero() {
    if (threadIdx.x < E_NUM) g_cnt[threadIdx.x] = 0;
}

// ---------------- kernel 1: router (logits + softmax + top-8 + renorm) ----------------
// one warp per token; lane = expert
__global__ void k_router(const float* __restrict__ x, const float* __restrict__ gw,
                         float* __restrict__ out, int write_ids) {
    int warp = (blockIdx.x * blockDim.x + threadIdx.x) >> 5;
    int lane = threadIdx.x & 31;
    if (warp >= T_TOK) return;

    const float* xr = x + (size_t)warp * H_DIM;
    float acc = 0.0f;
#pragma unroll 8
    for (int h = 0; h < H_DIM; h++) {
        acc += xr[h] * gw[h * E_NUM + lane];
    }

    // softmax over 32 lanes
    float m = acc;
#pragma unroll
    for (int o = 16; o; o >>= 1) m = fmaxf(m, __shfl_xor_sync(0xffffffffu, m, o));
    float p = expf(acc - m);
    float s = p;
#pragma unroll
    for (int o = 16; o; o >>= 1) s += __shfl_xor_sync(0xffffffffu, s, o);
    float score = p / s;

    // top-8, ties -> lowest index (matches jax.lax.top_k)
    float val = score;
    int   ids[TOPK];
    float ws[TOPK];
    float wsum = 0.0f;
#pragma unroll
    for (int j = 0; j < TOPK; j++) {
        float bv = val;
        int   bi = lane;
#pragma unroll
        for (int o = 16; o; o >>= 1) {
            float ov = __shfl_xor_sync(0xffffffffu, bv, o);
            int   oi = __shfl_xor_sync(0xffffffffu, bi, o);
            if (ov > bv || (ov == bv && oi < bi)) { bv = ov; bi = oi; }
        }
        ids[j] = bi; ws[j] = bv; wsum += bv;
        if (lane == bi) val = -1.0f;
    }

    if (lane == 0) {
        float inv = 1.0f / wsum;
#pragma unroll
        for (int j = 0; j < TOPK; j++) {
            g_topk_ids[warp * TOPK + j] = ids[j];
            g_topk_w[warp * TOPK + j]   = ws[j] * inv;
            atomicAdd(&g_cnt[ids[j]], 1);
            if (write_ids)
                out[(size_t)T_TOK * H_DIM + warp * TOPK + j] = (float)ids[j];
        }
    }
}

// ---------------- kernel 2: exclusive scan of counts ----------------
__global__ void k_scan() {
    if (threadIdx.x == 0) {
        int acc = 0;
        for (int e = 0; e < E_NUM; e++) {
            g_off[e] = acc;
            g_pos[e] = acc;
            acc += g_cnt[e];
        }
        g_off[E_NUM] = acc;
    }
}

// ---------------- kernel 3: scatter pairs into per-expert slots ----------------
__global__ void k_scatter() {
    int pp = blockIdx.x * blockDim.x + threadIdx.x;
    if (pp >= P_NUM) return;
    int e = g_topk_ids[pp];
    int slot = atomicAdd(&g_pos[e], 1);
    g_slot_token[slot] = pp >> 3;
    g_slot_w[slot]     = g_topk_w[pp];
    g_pair2slot[pp]    = slot;
}

// ---------------- kernel 4: fused gate+up GEMM + SwiGLU ----------------
// Per expert e: A = gathered tokens [cnt, H], Bg = w_gate[e] [H, I], Bu = w_up[e] [H, I]
// block tile 64(M) x 64(N) x 16(K), 8 warps (2x4), warp tile 32x16, double output (gate & up)
__global__ __launch_bounds__(256) void k_gemmA(const float* __restrict__ x,
                                               const float* __restrict__ wgate,
                                               const float* __restrict__ wup) {
    int e   = blockIdx.z;
    int cnt = g_cnt[e];
    int m0  = blockIdx.y * 64;
    if (m0 >= cnt) return;
    int n0   = blockIdx.x * 64;
    int base = g_off[e];
    int tid  = threadIdx.x;

    __shared__ uint32_t As[64 * 17];
    __shared__ uint32_t Bg[16 * 72];
    __shared__ uint32_t Bu[16 * 72];
    __shared__ int s_tok[64];

    if (tid < 64) {
        int m = m0 + tid;
        s_tok[tid] = g_slot_token[base + ((m < cnt) ? m : 0)];
    }
    __syncthreads();

    const float* wgb = wgate + (size_t)e * H_DIM * I_DIM + n0;
    const float* wub = wup   + (size_t)e * H_DIM * I_DIM + n0;

    int wid = tid >> 5, lane = tid & 31;
    int wm = (wid >> 2) * 32, wn = (wid & 3) * 16;
    int gid = lane >> 2, tig = lane & 3;

    float cg[2][2][4], cu[2][2][4];
#pragma unroll
    for (int a0 = 0; a0 < 2; a0++)
#pragma unroll
        for (int b0 = 0; b0 < 2; b0++)
#pragma unroll
            for (int c0 = 0; c0 < 4; c0++) { cg[a0][b0][c0] = 0.0f; cu[a0][b0][c0] = 0.0f; }

    int arow = tid >> 4, acol = tid & 15;   // A stage: 16 rows/pass x 16 cols
    int brow = tid >> 6, bcol = tid & 63;   // B stage: 4 rows/pass x 64 cols

    for (int k0 = 0; k0 < H_DIM; k0 += 16) {
#pragma unroll
        for (int i = 0; i < 4; i++) {
            int r = arow + i * 16;
            float v = x[(size_t)s_tok[r] * H_DIM + k0 + acol];
            As[r * 17 + acol] = f2tf(v);
        }
#pragma unroll
        for (int i = 0; i < 4; i++) {
            int kr = brow + i * 4;
            Bg[kr * 72 + bcol] = f2tf(wgb[(size_t)(k0 + kr) * I_DIM + bcol]);
            Bu[kr * 72 + bcol] = f2tf(wub[(size_t)(k0 + kr) * I_DIM + bcol]);
        }
        __syncthreads();

#pragma unroll
        for (int kf = 0; kf < 16; kf += 8) {
            uint32_t a[2][4], bg[2][2], bu[2][2];
#pragma unroll
            for (int mf = 0; mf < 2; mf++) {
                int rb = wm + mf * 16;
                a[mf][0] = As[(rb + gid) * 17 + kf + tig];
                a[mf][1] = As[(rb + gid + 8) * 17 + kf + tig];
                a[mf][2] = As[(rb + gid) * 17 + kf + tig + 4];
                a[mf][3] = As[(rb + gid + 8) * 17 + kf + tig + 4];
            }
#pragma unroll
            for (int nf = 0; nf < 2; nf++) {
                int cb = wn + nf * 8 + gid;
                bg[nf][0] = Bg[(kf + tig) * 72 + cb];
                bg[nf][1] = Bg[(kf + tig + 4) * 72 + cb];
                bu[nf][0] = Bu[(kf + tig) * 72 + cb];
                bu[nf][1] = Bu[(kf + tig + 4) * 72 + cb];
            }
#pragma unroll
            for (int mf = 0; mf < 2; mf++)
#pragma unroll
                for (int nf = 0; nf < 2; nf++) {
                    mma8(cg[mf][nf], a[mf], bg[nf]);
                    mma8(cu[mf][nf], a[mf], bu[nf]);
                }
        }
        __syncthreads();
    }

    // epilogue: h = silu(g) * u -> g_hbuf[slot, col]
#pragma unroll
    for (int mf = 0; mf < 2; mf++)
#pragma unroll
        for (int nf = 0; nf < 2; nf++) {
            int col = n0 + wn + nf * 8 + 2 * tig;
            int r1 = wm + mf * 16 + gid;
            int r2 = r1 + 8;
            int m1 = m0 + r1, m2 = m0 + r2;
            if (m1 < cnt) {
                float h0 = silu(cg[mf][nf][0]) * cu[mf][nf][0];
                float h1 = silu(cg[mf][nf][1]) * cu[mf][nf][1];
                float2 v = make_float2(h0, h1);
                *(float2*)&g_hbuf[(size_t)(base + m1) * I_DIM + col] = v;
            }
            if (m2 < cnt) {
                float h0 = silu(cg[mf][nf][2]) * cu[mf][nf][2];
                float h1 = silu(cg[mf][nf][3]) * cu[mf][nf][3];
                float2 v = make_float2(h0, h1);
                *(float2*)&g_hbuf[(size_t)(base + m2) * I_DIM + col] = v;
            }
        }
}

// ---------------- kernel 5: down GEMM, weighted, per-pair ----------------
// Per expert e: A = g_hbuf rows [cnt, I], B = w_down[e] [I, H]; D = w * (A@B) -> g_dbuf
__global__ __launch_bounds__(256) void k_gemmB(const float* __restrict__ wdown) {
    int e   = blockIdx.z;
    int cnt = g_cnt[e];
    int m0  = blockIdx.y * 64;
    if (m0 >= cnt) return;
    int n0   = blockIdx.x * 64;
    int base = g_off[e];
    int tid  = threadIdx.x;

    __shared__ uint32_t As[64 * 17];
    __shared__ uint32_t Bs[16 * 72];
    __shared__ int   s_slot[64];
    __shared__ float s_w[64];

    if (tid < 64) {
        int m = m0 + tid;
        int mc = (m < cnt) ? m : (cnt - 1);
        s_slot[tid] = base + mc;
        s_w[tid]    = g_slot_w[base + mc];
    }
    __syncthreads();

    const float* wb = wdown + (size_t)e * I_DIM * H_DIM + n0;

    int wid = tid >> 5, lane = tid & 31;
    int wm = (wid >> 2) * 32, wn = (wid & 3) * 16;
    int gid = lane >> 2, tig = lane & 3;

    float cc[2][2][4];
#pragma unroll
    for (int a0 = 0; a0 < 2; a0++)
#pragma unroll
        for (int b0 = 0; b0 < 2; b0++)
#pragma unroll
            for (int c0 = 0; c0 < 4; c0++) cc[a0][b0][c0] = 0.0f;

    int arow = tid >> 4, acol = tid & 15;
    int brow = tid >> 6, bcol = tid & 63;

    for (int k0 = 0; k0 < I_DIM; k0 += 16) {
#pragma unroll
        for (int i = 0; i < 4; i++) {
            int r = arow + i * 16;
            float v = g_hbuf[(size_t)s_slot[r] * I_DIM + k0 + acol];
            As[r * 17 + acol] = f2tf(v);
        }
#pragma unroll
        for (int i = 0; i < 4; i++) {
            int kr = brow + i * 4;
            Bs[kr * 72 + bcol] = f2tf(wb[(size_t)(k0 + kr) * H_DIM + bcol]);
        }
        __syncthreads();

#pragma unroll
        for (int kf = 0; kf < 16; kf += 8) {
            uint32_t a[2][4], b[2][2];
#pragma unroll
            for (int mf = 0; mf < 2; mf++) {
                int rb = wm + mf * 16;
                a[mf][0] = As[(rb + gid) * 17 + kf + tig];
                a[mf][1] = As[(rb + gid + 8) * 17 + kf + tig];
                a[mf][2] = As[(rb + gid) * 17 + kf + tig + 4];
                a[mf][3] = As[(rb + gid + 8) * 17 + kf + tig + 4];
            }
#pragma unroll
            for (int nf = 0; nf < 2; nf++) {
                int cb = wn + nf * 8 + gid;
                b[nf][0] = Bs[(kf + tig) * 72 + cb];
                b[nf][1] = Bs[(kf + tig + 4) * 72 + cb];
            }
#pragma unroll
            for (int mf = 0; mf < 2; mf++)
#pragma unroll
                for (int nf = 0; nf < 2; nf++) mma8(cc[mf][nf], a[mf], b[nf]);
        }
        __syncthreads();
    }

#pragma unroll
    for (int mf = 0; mf < 2; mf++)
#pragma unroll
        for (int nf = 0; nf < 2; nf++) {
            int col = n0 + wn + nf * 8 + 2 * tig;
            int r1 = wm + mf * 16 + gid;
            int r2 = r1 + 8;
            int m1 = m0 + r1, m2 = m0 + r2;
            if (m1 < cnt) {
                float w = s_w[r1];
                float2 v = make_float2(cc[mf][nf][0] * w, cc[mf][nf][1] * w);
                *(float2*)&g_dbuf[(size_t)(base + m1) * H_DIM + col] = v;
            }
            if (m2 < cnt) {
                float w = s_w[r2];
                float2 v = make_float2(cc[mf][nf][2] * w, cc[mf][nf][3] * w);
                *(float2*)&g_dbuf[(size_t)(base + m2) * H_DIM + col] = v;
            }
        }
}

// ---------------- kernel 6: deterministic 8-way combine per token ----------------
__global__ void k_reduce(float* __restrict__ out) {
    int idx = blockIdx.x * blockDim.x + threadIdx.x;  // [0, T*H)
    int t = idx >> 11;      // /H_DIM
    int h = idx & (H_DIM - 1);
    const int* ps = &g_pair2slot[t * TOPK];
    float s = 0.0f;
#pragma unroll
    for (int k = 0; k < TOPK; k++) s += g_dbuf[(size_t)ps[k] * H_DIM + h];
    out[idx] = s;
}

// ---------------- launch ----------------
extern "C" void kernel_launch(void* const* d_in, const int* in_sizes, int n_in,
                              void* d_out, int out_size) {
    const float* x  = (const float*)d_in[0];  // [T, H]
    const float* gw = (const float*)d_in[1];  // [H, E]
    const float* wg = (const float*)d_in[2];  // [E, H, I]
    const float* wu = (const float*)d_in[3];  // [E, H, I]
    const float* wd = (const float*)d_in[4];  // [E, I, H]
    float* out = (float*)d_out;

    int write_ids = (out_size >= T_TOK * H_DIM + P_NUM) ? 1 : 0;

    k_zero<<<1, 32>>>();
    k_router<<<T_TOK / 8, 256>>>(x, gw, out, write_ids);
    k_scan<<<1, 32>>>();
    k_scatter<<<P_NUM / 256, 256>>>();

    dim3 ga(I_DIM / 64, T_TOK / 64, E_NUM);  // (16, 64, 32)
    k_gemmA<<<ga, 256>>>(x, wg, wu);

    dim3 gb(H_DIM / 64, T_TOK / 64, E_NUM);  // (32, 64, 32)
    k_gemmB<<<gb, 256>>>(wd);

    k_reduce<<<(T_TOK * H_DIM) / 256, 256>>>(out);
}

// round 2
// speedup vs baseline: 2.1922x; 2.1922x over previous
#include <cuda_runtime.h>
#include <cstdint>
#include <math.h>

// Problem constants
#define T_TOK 4096
#define H_DIM 2048
#define E_NUM 32
#define I_DIM 1024
#define TOPK  8
#define P_NUM (T_TOK * TOPK)

// ---------------- scratch ----------------
__device__ int   g_topk_ids[P_NUM];
__device__ float g_topk_w[P_NUM];
__device__ int   g_cnt[E_NUM];
__device__ int   g_pos[E_NUM];
__device__ int   g_off[E_NUM + 1];
__device__ int   g_slot_token[P_NUM];
__device__ float g_slot_w[P_NUM];
__device__ int   g_pair2slot[P_NUM];
__device__ float g_hbuf[(size_t)P_NUM * I_DIM];
__device__ float g_dbuf[(size_t)P_NUM * H_DIM];

// ---------------- helpers ----------------
__device__ __forceinline__ uint32_t f2tf(float f) {
    uint32_t u;
    asm("cvt.rna.tf32.f32 %0, %1;" : "=r"(u) : "f"(f));
    return u;
}

__device__ __forceinline__ void mma8(float c[4], const uint32_t a[4], const uint32_t b[2]) {
    asm volatile(
        "mma.sync.aligned.m16n8k8.row.col.f32.tf32.tf32.f32 "
        "{%0,%1,%2,%3}, {%4,%5,%6,%7}, {%8,%9}, {%0,%1,%2,%3};\n"
        : "+f"(c[0]), "+f"(c[1]), "+f"(c[2]), "+f"(c[3])
        : "r"(a[0]), "r"(a[1]), "r"(a[2]), "r"(a[3]), "r"(b[0]), "r"(b[1]));
}

__device__ __forceinline__ void cpa16(uint32_t saddr, const void* g) {
    asm volatile("cp.async.cg.shared.global [%0], [%1], 16;" :: "r"(saddr), "l"(g));
}
#define CP_COMMIT() asm volatile("cp.async.commit_group;")
#define CP_WAIT(N)  asm volatile("cp.async.wait_group %0;" :: "n"(N))

__device__ __forceinline__ float silu(float x) {
    return x * (1.0f / (1.0f + __expf(-x)));
}

// ---------------- kernel 0 ----------------
__global__ void k_zero() {
    if (threadIdx.x < E_NUM) g_cnt[threadIdx.x] = 0;
}

// ---------------- kernel 1: router ----------------
__global__ void k_router(const float* __restrict__ x, const float* __restrict__ gw,
                         float* __restrict__ out, int write_ids) {
    int warp = (blockIdx.x * blockDim.x + threadIdx.x) >> 5;
    int lane = threadIdx.x & 31;
    if (warp >= T_TOK) return;

    const float* xr = x + (size_t)warp * H_DIM;
    float acc = 0.0f;
#pragma unroll 8
    for (int h = 0; h < H_DIM; h++) acc += xr[h] * gw[h * E_NUM + lane];

    float m = acc;
#pragma unroll
    for (int o = 16; o; o >>= 1) m = fmaxf(m, __shfl_xor_sync(0xffffffffu, m, o));
    float p = expf(acc - m);
    float s = p;
#pragma unroll
    for (int o = 16; o; o >>= 1) s += __shfl_xor_sync(0xffffffffu, s, o);
    float score = p / s;

    float val = score;
    int   ids[TOPK];
    float ws[TOPK];
    float wsum = 0.0f;
#pragma unroll
    for (int j = 0; j < TOPK; j++) {
        float bv = val;
        int   bi = lane;
#pragma unroll
        for (int o = 16; o; o >>= 1) {
            float ov = __shfl_xor_sync(0xffffffffu, bv, o);
            int   oi = __shfl_xor_sync(0xffffffffu, bi, o);
            if (ov > bv || (ov == bv && oi < bi)) { bv = ov; bi = oi; }
        }
        ids[j] = bi; ws[j] = bv; wsum += bv;
        if (lane == bi) val = -1.0f;
    }

    if (lane == 0) {
        float inv = 1.0f / wsum;
#pragma unroll
        for (int j = 0; j < TOPK; j++) {
            g_topk_ids[warp * TOPK + j] = ids[j];
            g_topk_w[warp * TOPK + j]   = ws[j] * inv;
            atomicAdd(&g_cnt[ids[j]], 1);
            if (write_ids)
                out[(size_t)T_TOK * H_DIM + warp * TOPK + j] = (float)ids[j];
        }
    }
}

// ---------------- kernel 2/3 ----------------
__global__ void k_scan() {
    if (threadIdx.x == 0) {
        int acc = 0;
        for (int e = 0; e < E_NUM; e++) { g_off[e] = acc; g_pos[e] = acc; acc += g_cnt[e]; }
        g_off[E_NUM] = acc;
    }
}

__global__ void k_scatter() {
    int pp = blockIdx.x * blockDim.x + threadIdx.x;
    if (pp >= P_NUM) return;
    int e = g_topk_ids[pp];
    int slot = atomicAdd(&g_pos[e], 1);
    g_slot_token[slot] = pp >> 3;
    g_slot_w[slot]     = g_topk_w[pp];
    g_pair2slot[pp]    = slot;
}

// ================= kernel 4: fused gate+up GEMM + SwiGLU =================
// Block 128M x 64N, BK=32, 2-stage cp.async pipeline, 8 warps (4M x 2N), warp 32x32.
#define A_STRIDE 36            // floats per A smem row (32 + pad)
#define A_TILE   (128 * A_STRIDE)   // 4608 floats / stage
#define BG_STRIDE 68           // floats per B smem row (64 + pad)
#define BG_TILE  (32 * BG_STRIDE)   // 2176 floats / stage

__global__ __launch_bounds__(256) void k_gemmA(const float* __restrict__ x,
                                               const float* __restrict__ wgate,
                                               const float* __restrict__ wup) {
    int e   = blockIdx.z;
    int cnt = g_cnt[e];
    int m0  = blockIdx.y * 128;
    if (m0 >= cnt) return;
    int n0   = blockIdx.x * 64;
    int base = g_off[e];
    int tid  = threadIdx.x;

    extern __shared__ float smem[];
    // layout: As[2] | Bg[2] | Bu[2]
    float* AsB = smem;
    float* BgB = smem + 2 * A_TILE;
    float* BuB = smem + 2 * A_TILE + 2 * BG_TILE;
    uint32_t sbase = (uint32_t)__cvta_generic_to_shared(smem);

    __shared__ int s_tok[128];
    if (tid < 128) {
        int m = m0 + tid;
        s_tok[tid] = g_slot_token[base + ((m < cnt) ? m : 0)];
    }
    __syncthreads();

    const float* wgb = wgate + (size_t)e * H_DIM * I_DIM + n0;
    const float* wub = wup   + (size_t)e * H_DIM * I_DIM + n0;

    // cp.async staging coords
    int ac = tid & 7,  ar = tid >> 3;     // A: 8 chunks/row, 32 rows/pass, 4 passes
    int bc = tid & 15, br = tid >> 4;     // B: 16 chunks/row, 16 rows/pass, 2 passes

    const int NT = H_DIM / 32;  // 64

    auto load_stage = [&](int t, int s) {
        int k0 = t * 32;
        uint32_t aoff = sbase + (uint32_t)(s * A_TILE) * 4u;
        uint32_t goff = sbase + (uint32_t)(2 * A_TILE + s * BG_TILE) * 4u;
        uint32_t uoff = sbase + (uint32_t)(2 * A_TILE + 2 * BG_TILE + s * BG_TILE) * 4u;
#pragma unroll
        for (int i = 0; i < 4; i++) {
            int r = ar + i * 32;
            const float* gp = x + (size_t)s_tok[r] * H_DIM + k0 + ac * 4;
            cpa16(aoff + (uint32_t)(r * A_STRIDE + ac * 4) * 4u, gp);
        }
#pragma unroll
        for (int i = 0; i < 2; i++) {
            int kr = br + i * 16;
            uint32_t so = (uint32_t)(kr * BG_STRIDE + bc * 4) * 4u;
            cpa16(goff + so, wgb + (size_t)(k0 + kr) * I_DIM + bc * 4);
            cpa16(uoff + so, wub + (size_t)(k0 + kr) * I_DIM + bc * 4);
        }
        CP_COMMIT();
    };

    int wid = tid >> 5, lane = tid & 31;
    int wm = (wid & 3) * 32, wn = (wid >> 2) * 32;
    int gid = lane >> 2, tig = lane & 3;

    float cg[2][4][4], cu[2][4][4];
#pragma unroll
    for (int i = 0; i < 2; i++)
#pragma unroll
        for (int j = 0; j < 4; j++)
#pragma unroll
            for (int q = 0; q < 4; q++) { cg[i][j][q] = 0.0f; cu[i][j][q] = 0.0f; }

    load_stage(0, 0);

    for (int t = 0; t < NT; t++) {
        if (t + 1 < NT) { load_stage(t + 1, (t + 1) & 1); CP_WAIT(1); }
        else            { CP_WAIT(0); }
        __syncthreads();

        const float* As = AsB + (t & 1) * A_TILE;
        const float* Bg = BgB + (t & 1) * BG_TILE;
        const float* Bu = BuB + (t & 1) * BG_TILE;

#pragma unroll
        for (int kf = 0; kf < 32; kf += 8) {
            uint32_t a[2][4];
#pragma unroll
            for (int mf = 0; mf < 2; mf++) {
                int rb = wm + mf * 16;
                a[mf][0] = f2tf(As[(rb + gid) * A_STRIDE + kf + tig]);
                a[mf][1] = f2tf(As[(rb + gid + 8) * A_STRIDE + kf + tig]);
                a[mf][2] = f2tf(As[(rb + gid) * A_STRIDE + kf + tig + 4]);
                a[mf][3] = f2tf(As[(rb + gid + 8) * A_STRIDE + kf + tig + 4]);
            }
            uint32_t bg[4][2], bu[4][2];
#pragma unroll
            for (int nf = 0; nf < 4; nf++) {
                int cb = wn + nf * 8 + gid;
                bg[nf][0] = f2tf(Bg[(kf + tig) * BG_STRIDE + cb]);
                bg[nf][1] = f2tf(Bg[(kf + tig + 4) * BG_STRIDE + cb]);
                bu[nf][0] = f2tf(Bu[(kf + tig) * BG_STRIDE + cb]);
                bu[nf][1] = f2tf(Bu[(kf + tig + 4) * BG_STRIDE + cb]);
            }
#pragma unroll
            for (int mf = 0; mf < 2; mf++)
#pragma unroll
                for (int nf = 0; nf < 4; nf++) {
                    mma8(cg[mf][nf], a[mf], bg[nf]);
                    mma8(cu[mf][nf], a[mf], bu[nf]);
                }
        }
        __syncthreads();
    }

    // epilogue
#pragma unroll
    for (int mf = 0; mf < 2; mf++)
#pragma unroll
        for (int nf = 0; nf < 4; nf++) {
            int col = n0 + wn + nf * 8 + 2 * tig;
            int r1 = wm + mf * 16 + gid;
            int r2 = r1 + 8;
            int m1 = m0 + r1, m2 = m0 + r2;
            if (m1 < cnt) {
                float2 v = make_float2(silu(cg[mf][nf][0]) * cu[mf][nf][0],
                                       silu(cg[mf][nf][1]) * cu[mf][nf][1]);
                *(float2*)&g_hbuf[(size_t)(base + m1) * I_DIM + col] = v;
            }
            if (m2 < cnt) {
                float2 v = make_float2(silu(cg[mf][nf][2]) * cu[mf][nf][2],
                                       silu(cg[mf][nf][3]) * cu[mf][nf][3]);
                *(float2*)&g_hbuf[(size_t)(base + m2) * I_DIM + col] = v;
            }
        }
}

// ================= kernel 5: down GEMM (weighted) =================
// Block 128M x 128N, BK=32, 2-stage cp.async, 8 warps (4M x 2N), warp 32x64.
#define BD_STRIDE 132
#define BD_TILE   (32 * BD_STRIDE)   // 4224 floats / stage

__global__ __launch_bounds__(256) void k_gemmB(const float* __restrict__ wdown) {
    int e   = blockIdx.z;
    int cnt = g_cnt[e];
    int m0  = blockIdx.y * 128;
    if (m0 >= cnt) return;
    int n0   = blockIdx.x * 128;
    int base = g_off[e];
    int tid  = threadIdx.x;

    extern __shared__ float smem[];
    float* AsB = smem;
    float* BsB = smem + 2 * A_TILE;
    uint32_t sbase = (uint32_t)__cvta_generic_to_shared(smem);

    const float* wb = wdown + (size_t)e * I_DIM * H_DIM + n0;

    int ac = tid & 7,  ar = tid >> 3;     // A: 8 chunks/row, 32 rows/pass, 4 passes
    int bc = tid & 31, br = tid >> 5;     // B: 32 chunks/row, 8 rows/pass, 4 passes

    const int NT = I_DIM / 32;  // 32

    auto load_stage = [&](int t, int s) {
        int k0 = t * 32;
        uint32_t aoff = sbase + (uint32_t)(s * A_TILE) * 4u;
        uint32_t boff = sbase + (uint32_t)(2 * A_TILE + s * BD_TILE) * 4u;
#pragma unroll
        for (int i = 0; i < 4; i++) {
            int r = ar + i * 32;
            int m = m0 + r;
            int slot = base + ((m < cnt) ? m : (cnt - 1));
            cpa16(aoff + (uint32_t)(r * A_STRIDE + ac * 4) * 4u,
                  &g_hbuf[(size_t)slot * I_DIM + k0 + ac * 4]);
        }
#pragma unroll
        for (int i = 0; i < 4; i++) {
            int kr = br + i * 8;
            cpa16(boff + (uint32_t)(kr * BD_STRIDE + bc * 4) * 4u,
                  wb + (size_t)(k0 + kr) * H_DIM + bc * 4);
        }
        CP_COMMIT();
    };

    int wid = tid >> 5, lane = tid & 31;
    int wm = (wid & 3) * 32, wn = (wid >> 2) * 64;
    int gid = lane >> 2, tig = lane & 3;

    float cc[2][8][4];
#pragma unroll
    for (int i = 0; i < 2; i++)
#pragma unroll
        for (int j = 0; j < 8; j++)
#pragma unroll
            for (int q = 0; q < 4; q++) cc[i][j][q] = 0.0f;

    load_stage(0, 0);

    for (int t = 0; t < NT; t++) {
        if (t + 1 < NT) { load_stage(t + 1, (t + 1) & 1); CP_WAIT(1); }
        else            { CP_WAIT(0); }
        __syncthreads();

        const float* As = AsB + (t & 1) * A_TILE;
        const float* Bs = BsB + (t & 1) * BD_TILE;

#pragma unroll
        for (int kf = 0; kf < 32; kf += 8) {
            uint32_t a[2][4];
#pragma unroll
            for (int mf = 0; mf < 2; mf++) {
                int rb = wm + mf * 16;
                a[mf][0] = f2tf(As[(rb + gid) * A_STRIDE + kf + tig]);
                a[mf][1] = f2tf(As[(rb + gid + 8) * A_STRIDE + kf + tig]);
                a[mf][2] = f2tf(As[(rb + gid) * A_STRIDE + kf + tig + 4]);
                a[mf][3] = f2tf(As[(rb + gid + 8) * A_STRIDE + kf + tig + 4]);
            }
            uint32_t b[8][2];
#pragma unroll
            for (int nf = 0; nf < 8; nf++) {
                int cb = wn + nf * 8 + gid;
                b[nf][0] = f2tf(Bs[(kf + tig) * BD_STRIDE + cb]);
                b[nf][1] = f2tf(Bs[(kf + tig + 4) * BD_STRIDE + cb]);
            }
#pragma unroll
            for (int mf = 0; mf < 2; mf++)
#pragma unroll
                for (int nf = 0; nf < 8; nf++) mma8(cc[mf][nf], a[mf], b[nf]);
        }
        __syncthreads();
    }

#pragma unroll
    for (int mf = 0; mf < 2; mf++) {
        int r1 = wm + mf * 16 + gid;
        int r2 = r1 + 8;
        int m1 = m0 + r1, m2 = m0 + r2;
        float w1 = (m1 < cnt) ? g_slot_w[base + m1] : 0.0f;
        float w2 = (m2 < cnt) ? g_slot_w[base + m2] : 0.0f;
#pragma unroll
        for (int nf = 0; nf < 8; nf++) {
            int col = n0 + wn + nf * 8 + 2 * tig;
            if (m1 < cnt) {
                float2 v = make_float2(cc[mf][nf][0] * w1, cc[mf][nf][1] * w1);
                *(float2*)&g_dbuf[(size_t)(base + m1) * H_DIM + col] = v;
            }
            if (m2 < cnt) {
                float2 v = make_float2(cc[mf][nf][2] * w2, cc[mf][nf][3] * w2);
                *(float2*)&g_dbuf[(size_t)(base + m2) * H_DIM + col] = v;
            }
        }
    }
}

// ---------------- kernel 6: combine (float4) ----------------
__global__ void k_reduce(float* __restrict__ out) {
    int idx4 = blockIdx.x * blockDim.x + threadIdx.x;  // over T*H/4
    int t  = idx4 >> 9;           // / (H_DIM/4)
    int h4 = idx4 & 511;
    const int* ps = &g_pair2slot[t * TOPK];
    float4 s = make_float4(0.f, 0.f, 0.f, 0.f);
#pragma unroll
    for (int k = 0; k < TOPK; k++) {
        const float4 v = *(const float4*)&g_dbuf[(size_t)ps[k] * H_DIM + h4 * 4];
        s.x += v.x; s.y += v.y; s.z += v.z; s.w += v.w;
    }
    *(float4*)&out[(size_t)idx4 * 4] = s;
}

// ---------------- launch ----------------
extern "C" void kernel_launch(void* const* d_in, const int* in_sizes, int n_in,
                              void* d_out, int out_size) {
    const float* x  = (const float*)d_in[0];
    const float* gw = (const float*)d_in[1];
    const float* wg = (const float*)d_in[2];
    const float* wu = (const float*)d_in[3];
    const float* wd = (const float*)d_in[4];
    float* out = (float*)d_out;

    int write_ids = (out_size >= T_TOK * H_DIM + P_NUM) ? 1 : 0;

    const int smemA = (2 * A_TILE + 4 * BG_TILE) * 4;   // 71680 B
    const int smemB = (2 * A_TILE + 2 * BD_TILE) * 4;   // 70656 B
    cudaFuncSetAttribute(k_gemmA, cudaFuncAttributeMaxDynamicSharedMemorySize, smemA);
    cudaFuncSetAttribute(k_gemmB, cudaFuncAttributeMaxDynamicSharedMemorySize, smemB);

    k_zero<<<1, 32>>>();
    k_router<<<T_TOK / 8, 256>>>(x, gw, out, write_ids);
    k_scan<<<1, 32>>>();
    k_scatter<<<P_NUM / 256, 256>>>();

    dim3 ga(I_DIM / 64, T_TOK / 128, E_NUM);   // (16, 32, 32)
    k_gemmA<<<ga, 256, smemA>>>(x, wg, wu);

    dim3 gb(H_DIM / 128, T_TOK / 128, E_NUM);  // (16, 32, 32)
    k_gemmB<<<gb, 256, smemB>>>(wd);

    k_reduce<<<(T_TOK * H_DIM / 4) / 256, 256>>>(out);
}